// round 16
// baseline (speedup 1.0000x reference)
#include <cuda_runtime.h>
#include <cstdint>

// ClusteringLayer: per-64-element-line greedy clustering, threshold 0.1f.
// Bases pairwise >= 0.1 apart => <=1 base per 0.1-wide RN bucket; matches
// confined to buckets k-1..k+1. Table entries PRE-ROTATED ror6 of
// {val rounded to 64 ulp | 6-bit order} (ord in MSBs; predicated-min probes).
// Quad-speculative resolve; cp.async.cg double-buffered stage-in;
// st.global.cs streaming stage-out. Empty = ror6(qNaN) (compare false).
// R16: EIGHTH-batch staging (1KB buffers) -> 10,240 B/warp -> 22 warps/SM.
// Hot quad body byte-identical to R15; only staging geometry changed.

#define THREADS   704           // 22 warps
#define WARPS     22
#define THRESH    0.1f
#define SROT      0x01FF0000u   // ror6(0x7FC00000 qNaN)

// RN bucket magic: fb = RN(x*10 + 2^23 + 32); k = low mantissa bits in [1,62]
#define BMAGIC    8388640.0f
#define BLO       8388609.0f
#define BHI       8388670.0f

// per-warp smem (bytes):
//   [0,    8192)  vals: u32[64][32] rotated entries   (bank==lane, CF)
//   [8192, 9216)  stgA: float4[32 lines][2 quads], swizzled (1KB)
//   [9216, 10240) stgB: second buffer
#define STGA_OFF   8192
#define STGB_OFF   9216
#define WARP_BYTES 10240
#define SMEM_TOTAL (WARP_BYTES * WARPS)     // 225280

extern __shared__ char smem_dyn[];

__device__ __forceinline__ int bucket_idx(float xi) {
    float fb = fmaf(xi, 10.0f, BMAGIC);
    fb = fminf(fmaxf(fb, BLO), BHI);
    return __float_as_int(fb) & 63;          // 1..62
}
__device__ __forceinline__ unsigned rol6(unsigned v) {
    return __funnelshift_l(v, v, 6);
}
// rotated new entry for (xi, e): ord<<26 | rounded-val>>6
__device__ __forceinline__ unsigned rpack(float xi, int e) {
    const unsigned nv = (__float_as_uint(xi) + 32u) & ~63u;
    return __funnelshift_r(nv | (unsigned)e, nv | (unsigned)e, 6);
}
// predicated-min probe: mk = min(mk, entry) iff entry value matches xi
__device__ __forceinline__ void probe_min(unsigned& mk, const unsigned* vals,
                                          int vi, float xi) {
    const unsigned ev = vals[vi];
    const float v = __uint_as_float(rol6(ev));
    if (fabsf(v - xi) < THRESH) mk = min(mk, ev);
}
__device__ __forceinline__ void stg_cs(float4* p, float4 v) {
    asm volatile("st.global.cs.v4.f32 [%0], {%1,%2,%3,%4};"
                 :: "l"(p), "f"(v.x), "f"(v.y), "f"(v.z), "f"(v.w) : "memory");
}

// async-copy one eighth (2 x 16B per thread = 1KB/warp) into a staging buffer
// swizzle: f = l*2 + (q ^ ((l>>2)&1))  -- CF on all access patterns
template <bool FULL>
__device__ __forceinline__ void issue_eighth(float4* dstbuf, const float4* gin,
                                             int h, int nvalid, int lane) {
    #pragma unroll
    for (int c = 0; c < 2; c++) {
        const int idx = c * 32 + lane;       // 0..63
        const int l   = idx >> 1;
        const int q   = idx & 1;
        if (FULL || l < nvalid) {
            const uint32_t dst = (uint32_t)__cvta_generic_to_shared(
                dstbuf + l * 2 + (q ^ ((l >> 2) & 1)));
            asm volatile("cp.async.cg.shared.global [%0], [%1], 16;"
                         :: "r"(dst), "l"(gin + l * 16 + 2 * h + q));
        }
    }
    asm volatile("cp.async.commit_group;");
}

// process one 8-element eighth + streaming stage-out (quad body == R15)
template <bool FULL>
__device__ __forceinline__ void process_and_flush(
    unsigned* vals, float4* stg4, float4* gout,
    int h, int nvalid, int lane, int lsw)
{
    if (FULL || lane < nvalid) {
        #pragma unroll 1
        for (int qi = 0; qi < 2; qi++) {
            const int sidx = lane * 2 + (qi ^ lsw);
            float4 xv = stg4[sidx];
            const float x0 = xv.x, x1 = xv.y, x2 = xv.z, x3 = xv.w;
            const int e0 = 8 * h + 4 * qi;

            const int vi0 = bucket_idx(x0) * 32 + lane;
            const int vi1 = bucket_idx(x1) * 32 + lane;
            const int vi2 = bucket_idx(x2) * 32 + lane;
            const int vi3 = bucket_idx(x3) * 32 + lane;

            // 12 probes on pre-quad state (latency overlapped)
            unsigned mk0 = 0xFFFFFFFFu, mk1 = 0xFFFFFFFFu;
            unsigned mk2 = 0xFFFFFFFFu, mk3 = 0xFFFFFFFFu;
            probe_min(mk0, vals, vi0 - 32, x0);
            probe_min(mk0, vals, vi0,      x0);
            probe_min(mk0, vals, vi0 + 32, x0);
            probe_min(mk1, vals, vi1 - 32, x1);
            probe_min(mk1, vals, vi1,      x1);
            probe_min(mk1, vals, vi1 + 32, x1);
            probe_min(mk2, vals, vi2 - 32, x2);
            probe_min(mk2, vals, vi2,      x2);
            probe_min(mk2, vals, vi2 + 32, x2);
            probe_min(mk3, vals, vi3 - 32, x3);
            probe_min(mk3, vals, vi3,      x3);
            probe_min(mk3, vals, vi3 + 32, x3);

            // register-only resolve with cross-candidates (rotated domain)
            const bool f0 = (mk0 != 0xFFFFFFFFu);
            const unsigned ro0 = rpack(x0, e0);
            const unsigned r0m = f0 ? 0xFFFFFFFFu : ro0;

            const unsigned c01 = (fabsf(x0 - x1) < THRESH) ? r0m : 0xFFFFFFFFu;
            const unsigned m1  = min(mk1, c01);
            const bool f1 = (m1 != 0xFFFFFFFFu);
            const unsigned ro1 = rpack(x1, e0 + 1);
            const unsigned r1m = f1 ? 0xFFFFFFFFu : ro1;

            const unsigned c02 = (fabsf(x0 - x2) < THRESH) ? r0m : 0xFFFFFFFFu;
            const unsigned c12 = (fabsf(x1 - x2) < THRESH) ? r1m : 0xFFFFFFFFu;
            const unsigned m2  = min(min(mk2, c02), c12);
            const bool f2 = (m2 != 0xFFFFFFFFu);
            const unsigned ro2 = rpack(x2, e0 + 2);
            const unsigned r2m = f2 ? 0xFFFFFFFFu : ro2;

            const unsigned c03 = (fabsf(x0 - x3) < THRESH) ? r0m : 0xFFFFFFFFu;
            const unsigned c13 = (fabsf(x1 - x3) < THRESH) ? r1m : 0xFFFFFFFFu;
            const unsigned c23 = (fabsf(x2 - x3) < THRESH) ? r2m : 0xFFFFFFFFu;
            const unsigned m3  = min(min(min(mk3, c03), c13), c23);
            const bool f3 = (m3 != 0xFFFFFFFFu);
            const unsigned ro3 = rpack(x3, e0 + 3);

            float4 ov;
            ov.x = f0 ? __uint_as_float(rol6(mk0)) : x0;
            ov.y = f1 ? __uint_as_float(rol6(m1))  : x1;
            ov.z = f2 ? __uint_as_float(rol6(m2))  : x2;
            ov.w = f3 ? __uint_as_float(rol6(m3))  : x3;
            stg4[sidx] = ov;

            // predicated inserts (distinct buckets guaranteed within quad)
            if (!f0) vals[vi0] = ro0;
            if (!f1) vals[vi1] = ro1;
            if (!f2) vals[vi2] = ro2;
            if (!f3) vals[vi3] = ro3;
        }
    }
    __syncwarp();

    // stage out: swizzled LDS.128 (CF), coalesced streaming STG.128
    #pragma unroll
    for (int c = 0; c < 2; c++) {
        const int idx = c * 32 + lane;
        const int l   = idx >> 1;
        const int q   = idx & 1;
        if (FULL || l < nvalid)
            stg_cs(gout + l * 16 + 2 * h + q,
                   stg4[l * 2 + (q ^ ((l >> 2) & 1))]);
    }
    __syncwarp();   // all lanes done with this buffer before it refills
}

__global__ void __launch_bounds__(THREADS, 1)
cluster_kernel(const float* __restrict__ x, float* __restrict__ out, long n)
{
    const int tid  = threadIdx.x;
    const int wid  = tid >> 5;
    const int lane = tid & 31;

    char*     wbase = smem_dyn + (long)wid * WARP_BYTES;
    unsigned* vals  = (unsigned*)wbase;
    float4*   bufs[2] = { (float4*)(wbase + STGA_OFF),
                          (float4*)(wbase + STGB_OFF) };

    const uint4 sent4 = make_uint4(SROT, SROT, SROT, SROT);
    {
        uint4* vp = (uint4*)vals;
        #pragma unroll
        for (int j = 0; j < 16; j++) vp[j * 32 + lane] = sent4;
    }
    __syncwarp();

    const long n_lines = n >> 6;

    // tail copy (n % 64; zero for this shape, kept for generality)
    {
        const long tail0 = n_lines << 6;
        for (long t = (long)blockIdx.x * blockDim.x + tid + tail0; t < n;
             t += (long)gridDim.x * blockDim.x)
            out[t] = x[t];
    }

    const long n_batches = (n_lines + 31) >> 5;
    const long gwarp = (long)blockIdx.x * WARPS + wid;
    const long nwarp = (long)gridDim.x * WARPS;
    const int  lsw   = (lane >> 2) & 1;

    int cur = 0;

    // prologue: start eighth 0 of first batch
    if (gwarp < n_batches) {
        const long line0 = gwarp << 5;
        long nv_l = n_lines - line0;
        const int nv = (nv_l >= 32) ? 32 : (int)nv_l;
        if (nv == 32)
            issue_eighth<true >(bufs[0], (const float4*)x + (line0 << 4), 0, 32, lane);
        else
            issue_eighth<false>(bufs[0], (const float4*)x + (line0 << 4), 0, nv, lane);
    }

    for (long b = gwarp; b < n_batches; b += nwarp) {
        const long line0 = b << 5;
        const float4* gin  = (const float4*)x   + (line0 << 4);
        float4*       gout = (float4*)out       + (line0 << 4);
        long nv_l = n_lines - line0;
        const int nvalid = (nv_l >= 32) ? 32 : (int)nv_l;
        const bool full = (nvalid == 32);

        #pragma unroll 1
        for (int h = 0; h < 8; h++) {
            // issue next eighth into the other buffer, then wait for current
            if (h < 7) {
                if (full) issue_eighth<true >(bufs[cur ^ 1], gin, h + 1, 32,     lane);
                else      issue_eighth<false>(bufs[cur ^ 1], gin, h + 1, nvalid, lane);
                asm volatile("cp.async.wait_group 1;");
            } else {
                const long bn = b + nwarp;
                if (bn < n_batches) {
                    const long l0n = bn << 5;
                    long nvn_l = n_lines - l0n;
                    const int nvn = (nvn_l >= 32) ? 32 : (int)nvn_l;
                    if (nvn == 32)
                        issue_eighth<true >(bufs[cur ^ 1],
                                            (const float4*)x + (l0n << 4), 0, 32, lane);
                    else
                        issue_eighth<false>(bufs[cur ^ 1],
                                            (const float4*)x + (l0n << 4), 0, nvn, lane);
                    asm volatile("cp.async.wait_group 1;");
                } else {
                    asm volatile("cp.async.wait_group 0;");
                }
            }
            __syncwarp();

            if (full)
                process_and_flush<true >(vals, bufs[cur], gout, h, 32,     lane, lsw);
            else
                process_and_flush<false>(vals, bufs[cur], gout, h, nvalid, lane, lsw);

            cur ^= 1;
        }

        // bulk cleanup: wipe table to sentinel (coalesced STS.128)
        {
            uint4* vp = (uint4*)vals;
            #pragma unroll
            for (int j = 0; j < 16; j++) vp[j * 32 + lane] = sent4;
        }
        __syncwarp();
    }
}

extern "C" void kernel_launch(void* const* d_in, const int* in_sizes, int n_in,
                              void* d_out, int out_size)
{
    (void)n_in; (void)out_size;
    const float* x = (const float*)d_in[0];
    float* out = (float*)d_out;
    const long n = (long)in_sizes[0];

    cudaFuncSetAttribute(cluster_kernel,
                         cudaFuncAttributeMaxDynamicSharedMemorySize, SMEM_TOTAL);

    cluster_kernel<<<148, THREADS, SMEM_TOTAL>>>(x, out, n);
}

// round 17
// speedup vs baseline: 1.2770x; 1.2770x over previous
#include <cuda_runtime.h>
#include <cstdint>

// ClusteringLayer: per-64-element-line greedy clustering, threshold 0.1f.
// Bases pairwise >= 0.1 apart => <=1 base per 0.1-wide RN bucket; matches
// confined to buckets k-1..k+1. Table entries PRE-ROTATED ror6 of
// {val rounded to 64 ulp | 6-bit order} (ord in MSBs; predicated-min probes).
// Quad-speculative resolve; cp.async.cg double-buffered QUARTER stage-in;
// st.global.cs streaming stage-out. Empty = ror6(qNaN) (compare false).
// R17: DYNAMIC WORK STEALING — per-batch ticket from a global atomic counter
// (reset by a tiny pre-kernel for graph-replay determinism). Removes the
// static 10-vs-9 batch tail (+6.2%) and equalizes cross-SM spread.
// Hot loop and staging geometry byte-identical to R15 (best: 102.4us).

#define THREADS   576           // 18 warps
#define WARPS     18
#define THRESH    0.1f
#define SROT      0x01FF0000u   // ror6(0x7FC00000 qNaN)

// RN bucket magic: fb = RN(x*10 + 2^23 + 32); k = low mantissa bits in [1,62]
#define BMAGIC    8388640.0f
#define BLO       8388609.0f
#define BHI       8388670.0f

// per-warp smem (bytes):
//   [0,     8192)  vals: u32[64][32] rotated entries   (bank==lane, CF)
//   [8192,  10240) stgA: float4[32 lines][1 quarter], swizzled
//   [10240, 12288) stgB: second buffer (double buffering)
#define STGA_OFF   8192
#define STGB_OFF   10240
#define WARP_BYTES 12288
#define SMEM_TOTAL (WARP_BYTES * WARPS)     // 221184

extern __shared__ char smem_dyn[];

__device__ unsigned g_ctr;                   // work-stealing ticket counter

__global__ void reset_ctr() { g_ctr = 0u; }

__device__ __forceinline__ long draw_batch(int lane) {
    unsigned t = 0;
    if (lane == 0) t = atomicAdd(&g_ctr, 1u);
    t = __shfl_sync(0xFFFFFFFFu, t, 0);
    return (long)t;
}

__device__ __forceinline__ int bucket_idx(float xi) {
    float fb = fmaf(xi, 10.0f, BMAGIC);
    fb = fminf(fmaxf(fb, BLO), BHI);
    return __float_as_int(fb) & 63;          // 1..62
}
__device__ __forceinline__ unsigned rol6(unsigned v) {
    return __funnelshift_l(v, v, 6);
}
// rotated new entry for (xi, e): ord<<26 | rounded-val>>6
__device__ __forceinline__ unsigned rpack(float xi, int e) {
    const unsigned nv = (__float_as_uint(xi) + 32u) & ~63u;
    return __funnelshift_r(nv | (unsigned)e, nv | (unsigned)e, 6);
}
// predicated-min probe: mk = min(mk, entry) iff entry value matches xi
__device__ __forceinline__ void probe_min(unsigned& mk, const unsigned* vals,
                                          int vi, float xi) {
    const unsigned ev = vals[vi];
    const float v = __uint_as_float(rol6(ev));
    if (fabsf(v - xi) < THRESH) mk = min(mk, ev);
}
__device__ __forceinline__ void stg_cs(float4* p, float4 v) {
    asm volatile("st.global.cs.v4.f32 [%0], {%1,%2,%3,%4};"
                 :: "l"(p), "f"(v.x), "f"(v.y), "f"(v.z), "f"(v.w) : "memory");
}

// async-copy one quarter (4 x 16B per thread) into a staging buffer
template <bool FULL>
__device__ __forceinline__ void issue_quarter(float4* dstbuf, const float4* gin,
                                              int h, int nvalid, int lane) {
    #pragma unroll
    for (int c = 0; c < 4; c++) {
        const int idx = c * 32 + lane;
        const int l   = idx >> 2;
        const int q   = idx & 3;
        if (FULL || l < nvalid) {
            const uint32_t dst = (uint32_t)__cvta_generic_to_shared(
                dstbuf + l * 4 + (q ^ ((l >> 1) & 3)));
            asm volatile("cp.async.cg.shared.global [%0], [%1], 16;"
                         :: "r"(dst), "l"(gin + l * 16 + 4 * h + q));
        }
    }
    asm volatile("cp.async.commit_group;");
}

// process one 16-element quarter + streaming stage-out (hot loop == R15)
template <bool FULL>
__device__ __forceinline__ void process_and_flush(
    unsigned* vals, float4* stg4, float4* gout,
    int h, int nvalid, int lane, int lsw2)
{
    if (FULL || lane < nvalid) {
        #pragma unroll 1
        for (int qi = 0; qi < 4; qi++) {
            const int sidx = lane * 4 + (qi ^ lsw2);
            float4 xv = stg4[sidx];
            const float x0 = xv.x, x1 = xv.y, x2 = xv.z, x3 = xv.w;
            const int e0 = 16 * h + 4 * qi;

            const int vi0 = bucket_idx(x0) * 32 + lane;
            const int vi1 = bucket_idx(x1) * 32 + lane;
            const int vi2 = bucket_idx(x2) * 32 + lane;
            const int vi3 = bucket_idx(x3) * 32 + lane;

            // 12 probes on pre-quad state (latency overlapped)
            unsigned mk0 = 0xFFFFFFFFu, mk1 = 0xFFFFFFFFu;
            unsigned mk2 = 0xFFFFFFFFu, mk3 = 0xFFFFFFFFu;
            probe_min(mk0, vals, vi0 - 32, x0);
            probe_min(mk0, vals, vi0,      x0);
            probe_min(mk0, vals, vi0 + 32, x0);
            probe_min(mk1, vals, vi1 - 32, x1);
            probe_min(mk1, vals, vi1,      x1);
            probe_min(mk1, vals, vi1 + 32, x1);
            probe_min(mk2, vals, vi2 - 32, x2);
            probe_min(mk2, vals, vi2,      x2);
            probe_min(mk2, vals, vi2 + 32, x2);
            probe_min(mk3, vals, vi3 - 32, x3);
            probe_min(mk3, vals, vi3,      x3);
            probe_min(mk3, vals, vi3 + 32, x3);

            // register-only resolve with cross-candidates (rotated domain)
            const bool f0 = (mk0 != 0xFFFFFFFFu);
            const unsigned ro0 = rpack(x0, e0);
            const unsigned r0m = f0 ? 0xFFFFFFFFu : ro0;

            const unsigned c01 = (fabsf(x0 - x1) < THRESH) ? r0m : 0xFFFFFFFFu;
            const unsigned m1  = min(mk1, c01);
            const bool f1 = (m1 != 0xFFFFFFFFu);
            const unsigned ro1 = rpack(x1, e0 + 1);
            const unsigned r1m = f1 ? 0xFFFFFFFFu : ro1;

            const unsigned c02 = (fabsf(x0 - x2) < THRESH) ? r0m : 0xFFFFFFFFu;
            const unsigned c12 = (fabsf(x1 - x2) < THRESH) ? r1m : 0xFFFFFFFFu;
            const unsigned m2  = min(min(mk2, c02), c12);
            const bool f2 = (m2 != 0xFFFFFFFFu);
            const unsigned ro2 = rpack(x2, e0 + 2);
            const unsigned r2m = f2 ? 0xFFFFFFFFu : ro2;

            const unsigned c03 = (fabsf(x0 - x3) < THRESH) ? r0m : 0xFFFFFFFFu;
            const unsigned c13 = (fabsf(x1 - x3) < THRESH) ? r1m : 0xFFFFFFFFu;
            const unsigned c23 = (fabsf(x2 - x3) < THRESH) ? r2m : 0xFFFFFFFFu;
            const unsigned m3  = min(min(min(mk3, c03), c13), c23);
            const bool f3 = (m3 != 0xFFFFFFFFu);
            const unsigned ro3 = rpack(x3, e0 + 3);

            float4 ov;
            ov.x = f0 ? __uint_as_float(rol6(mk0)) : x0;
            ov.y = f1 ? __uint_as_float(rol6(m1))  : x1;
            ov.z = f2 ? __uint_as_float(rol6(m2))  : x2;
            ov.w = f3 ? __uint_as_float(rol6(m3))  : x3;
            stg4[sidx] = ov;

            // predicated inserts (distinct buckets guaranteed within quad)
            if (!f0) vals[vi0] = ro0;
            if (!f1) vals[vi1] = ro1;
            if (!f2) vals[vi2] = ro2;
            if (!f3) vals[vi3] = ro3;
        }
    }
    __syncwarp();

    // stage out: swizzled LDS.128 (CF), coalesced streaming STG.128
    #pragma unroll
    for (int c = 0; c < 4; c++) {
        const int idx = c * 32 + lane;
        const int l   = idx >> 2;
        const int q   = idx & 3;
        if (FULL || l < nvalid)
            stg_cs(gout + l * 16 + 4 * h + q,
                   stg4[l * 4 + (q ^ ((l >> 1) & 3))]);
    }
    __syncwarp();   // all lanes done with this buffer before it refills
}

__global__ void __launch_bounds__(THREADS, 1)
cluster_kernel(const float* __restrict__ x, float* __restrict__ out, long n)
{
    const int tid  = threadIdx.x;
    const int wid  = tid >> 5;
    const int lane = tid & 31;

    char*     wbase = smem_dyn + (long)wid * WARP_BYTES;
    unsigned* vals  = (unsigned*)wbase;
    float4*   bufs[2] = { (float4*)(wbase + STGA_OFF),
                          (float4*)(wbase + STGB_OFF) };

    const uint4 sent4 = make_uint4(SROT, SROT, SROT, SROT);
    {
        uint4* vp = (uint4*)vals;
        #pragma unroll
        for (int j = 0; j < 16; j++) vp[j * 32 + lane] = sent4;
    }
    __syncwarp();

    const long n_lines = n >> 6;

    // tail copy (n % 64; zero for this shape, kept for generality)
    {
        const long tail0 = n_lines << 6;
        for (long t = (long)blockIdx.x * blockDim.x + tid + tail0; t < n;
             t += (long)gridDim.x * blockDim.x)
            out[t] = x[t];
    }

    const long n_batches = (n_lines + 31) >> 5;
    const int  lsw2  = (lane >> 1) & 3;

    int cur = 0;

    // prologue: draw first batch, prefetch its quarter 0
    long b = draw_batch(lane);
    if (b < n_batches) {
        const long line0 = b << 5;
        long nv_l = n_lines - line0;
        const int nv = (nv_l >= 32) ? 32 : (int)nv_l;
        if (nv == 32)
            issue_quarter<true >(bufs[0], (const float4*)x + (line0 << 4), 0, 32, lane);
        else
            issue_quarter<false>(bufs[0], (const float4*)x + (line0 << 4), 0, nv, lane);
    }

    while (b < n_batches) {
        // draw the NEXT batch now; its id is needed at h==3 for prefetch
        const long nb = draw_batch(lane);

        const long line0 = b << 5;
        const float4* gin  = (const float4*)x   + (line0 << 4);
        float4*       gout = (float4*)out       + (line0 << 4);
        long nv_l = n_lines - line0;
        const int nvalid = (nv_l >= 32) ? 32 : (int)nv_l;
        const bool full = (nvalid == 32);

        #pragma unroll
        for (int h = 0; h < 4; h++) {
            // issue next quarter into the other buffer, then wait for current
            if (h < 3) {
                if (full) issue_quarter<true >(bufs[cur ^ 1], gin, h + 1, 32,     lane);
                else      issue_quarter<false>(bufs[cur ^ 1], gin, h + 1, nvalid, lane);
                asm volatile("cp.async.wait_group 1;");
            } else {
                if (nb < n_batches) {
                    const long l0n = nb << 5;
                    long nvn_l = n_lines - l0n;
                    const int nvn = (nvn_l >= 32) ? 32 : (int)nvn_l;
                    if (nvn == 32)
                        issue_quarter<true >(bufs[cur ^ 1],
                                             (const float4*)x + (l0n << 4), 0, 32, lane);
                    else
                        issue_quarter<false>(bufs[cur ^ 1],
                                             (const float4*)x + (l0n << 4), 0, nvn, lane);
                    asm volatile("cp.async.wait_group 1;");
                } else {
                    asm volatile("cp.async.wait_group 0;");
                }
            }
            __syncwarp();

            if (full)
                process_and_flush<true >(vals, bufs[cur], gout, h, 32,     lane, lsw2);
            else
                process_and_flush<false>(vals, bufs[cur], gout, h, nvalid, lane, lsw2);

            cur ^= 1;
        }

        // bulk cleanup: wipe table to sentinel (coalesced STS.128)
        {
            uint4* vp = (uint4*)vals;
            #pragma unroll
            for (int j = 0; j < 16; j++) vp[j * 32 + lane] = sent4;
        }
        __syncwarp();

        b = nb;
    }
}

extern "C" void kernel_launch(void* const* d_in, const int* in_sizes, int n_in,
                              void* d_out, int out_size)
{
    (void)n_in; (void)out_size;
    const float* x = (const float*)d_in[0];
    float* out = (float*)d_out;
    const long n = (long)in_sizes[0];

    cudaFuncSetAttribute(cluster_kernel,
                         cudaFuncAttributeMaxDynamicSharedMemorySize, SMEM_TOTAL);

    // reset the ticket counter每 launch (same stream -> ordered; capture-safe)
    reset_ctr<<<1, 1>>>();
    cluster_kernel<<<148, THREADS, SMEM_TOTAL>>>(x, out, n);
}